// round 10
// baseline (speedup 1.0000x reference)
#include <cuda_runtime.h>
#include <cstdint>
#include <cstddef>

// ---------------------------------------------------------------------------
// 2-layer LSTM (T=512, B=4096, D=64, H=70) + MLP head.
// R9: R8 cluster-split recurrence + exit-safety fix (unconditional arrive at
//     loop end + final cluster wait before exit, so peer DSMEM stores land
//     before any CTA deallocates its SMEM).
// ---------------------------------------------------------------------------

#define TT   512
#define BB   4096
#define DD   64
#define HH   70
#define GP   288          // padded gate cols (4*72), col = 4n + gate
#define NTHR 256
#define NPERS 148         // persistent gemm CTAs
#define RTHR 288          // recurrence threads (9 warps)
#define RBLK 128          // recurrence CTAs (64 clusters of 2)

typedef unsigned long long u64;

// scratch: gate-x buffer [T][288][B] (reused for both layers),
//          h0 sequence [T][70][B], final h1 [70][B]
__device__ float g_gx[(size_t)TT * GP * BB];
__device__ float g_h0[(size_t)TT * HH * BB];
__device__ float g_h1[HH * BB];

#define FMA2A(d, a, b) \
    asm("fma.rn.f32x2 %0, %1, %2, %0;" : "+l"(d) : "l"(a), "l"(b))

#define CP16(dst_u32, src) \
    asm volatile("cp.async.ca.shared.global [%0], [%1], 16;" \
                 :: "r"(dst_u32), "l"(src))
#define CP_COMMIT() asm volatile("cp.async.commit_group;")
#define CP_WAIT0()  asm volatile("cp.async.wait_group 0;")
#define CP_WAIT1()  asm volatile("cp.async.wait_group 1;")

__device__ __forceinline__ u64 dup2(float v) {
    u64 r;
    unsigned int u = __float_as_uint(v);
    asm("mov.b64 %0, {%1,%2};" : "=l"(r) : "r"(u), "r"(u));
    return r;
}
__device__ __forceinline__ u64 pack2f(float lo, float hi) {
    u64 r;
    asm("mov.b64 %0, {%1,%2};" : "=l"(r)
        : "r"(__float_as_uint(lo)), "r"(__float_as_uint(hi)));
    return r;
}
__device__ __forceinline__ void unpack2f(u64 v, float& lo, float& hi) {
    unsigned int a, b;
    asm("mov.b64 {%0,%1}, %2;" : "=r"(a), "=r"(b) : "l"(v));
    lo = __uint_as_float(a);
    hi = __uint_as_float(b);
}

// FMA-only activations (no MUFU; proven rel_err ~1e-7)
__device__ __forceinline__ float fexp2s(float y) {
    y = fminf(fmaxf(y, -28.0f), 28.0f);
    float t = __fadd_rn(y, 12582912.0f);
    int   n = __float_as_int(t) - 0x4B400000;
    float f = __fsub_rn(y, __fsub_rn(t, 12582912.0f));
    float p =            1.54035304e-4f;
    p = __fmaf_rn(p, f,  1.33335581e-3f);
    p = __fmaf_rn(p, f,  9.61812911e-3f);
    p = __fmaf_rn(p, f,  5.55041087e-2f);
    p = __fmaf_rn(p, f,  2.40226507e-1f);
    p = __fmaf_rn(p, f,  6.93147181e-1f);
    p = __fmaf_rn(p, f,  1.0f);
    return __int_as_float(__float_as_int(p) + (n << 23));
}
__device__ __forceinline__ float frcps(float a) {
    float x = __int_as_float(0x7EF311C3 - __float_as_int(a));
    x = x * __fmaf_rn(-a, x, 2.0f);
    x = x * __fmaf_rn(-a, x, 2.0f);
    x = x * __fmaf_rn(-a, x, 2.0f);
    return x;
}
__device__ __forceinline__ float sigm(float x) {
    return frcps(1.0f + fexp2s(x * -1.44269504f));
}
__device__ __forceinline__ float tanh_(float x) {
    return 1.0f - 2.0f * frcps(1.0f + fexp2s(x * 2.88539008f));
}

// gate-major row j -> interleaved column
__device__ __forceinline__ int gcol(int j) {
    int g = j / HH, n = j - g * HH;
    return 4 * n + g;
}

__device__ __forceinline__ uint32_t smem_u32(const void* p) {
    return (uint32_t)__cvta_generic_to_shared(p);
}
__device__ __forceinline__ uint32_t mapa_peer(uint32_t laddr, uint32_t peer) {
    uint32_t r;
    asm("mapa.shared::cluster.u32 %0, %1, %2;" : "=r"(r)
        : "r"(laddr), "r"(peer));
    return r;
}
#define STS_CLUSTER(addr, v) \
    asm volatile("st.shared::cluster.f32 [%0], %1;" :: "r"(addr), "f"(v) : "memory")
#define CLU_ARRIVE() asm volatile("barrier.cluster.arrive.aligned;" ::: "memory")
#define CLU_WAIT()   asm volatile("barrier.cluster.wait.aligned;" ::: "memory")

// ---------------------------------------------------------------------------
// gx = X @ W^T + (b1 + b2), output layout [T][GP][B].  (R7, unchanged)
// ---------------------------------------------------------------------------
template <int KK, bool XTB>
__global__ void __launch_bounds__(NTHR, 1)
gemm_x(const float* __restrict__ X, const float* __restrict__ W,
       const float* __restrict__ b1, const float* __restrict__ b2,
       float* __restrict__ gx)
{
    constexpr int XS_ELEMS = XTB ? (64 * 68) : (KK * 64);

    extern __shared__ float sm[];
    float* Wt   = sm;
    float* bias = Wt + KK * GP;
    float* xsA  = bias + GP;
    float* xsB  = xsA + XS_ELEMS;

    const int tid  = threadIdx.x;
    const int lane = tid & 31;
    const int w    = tid >> 5;

    for (int i = tid; i < (KK + 1) * GP; i += NTHR) sm[i] = 0.f;
    __syncthreads();
    for (int idx = tid; idx < 4 * HH * KK; idx += NTHR) {
        int j = idx / KK, k = idx - j * KK;
        Wt[k * GP + gcol(j)] = W[idx];
    }
    for (int j = tid; j < 4 * HH; j += NTHR)
        bias[gcol(j)] = b1[j] + b2[j];
    __syncthreads();

    const ulonglong2* bp =
        reinterpret_cast<const ulonglong2*>(bias + w * 36);
    const float* Wrow = Wt + w * 36;

    const int ntiles = (TT * BB) / 64;

    auto stage = [&](int tile, float* buf) {
        const int m0 = tile * 64;
        const int t  = m0 >> 12;
        const int b0 = m0 & 4095;
        if (XTB) {
#pragma unroll
            for (int ii = 0; ii < (64 * 16) / NTHR; ii++) {
                int idx = tid + ii * NTHR;
                int r = idx >> 4, c = idx & 15;
                int cs = c ^ ((r >> 3) & 3);
                const float* src = X + ((size_t)t * BB + b0 + r) * KK + c * 4;
                CP16(smem_u32(buf + r * 68 + cs * 4), src);
            }
        } else {
#pragma unroll
            for (int ii = 0; ii < (KK * 16 + NTHR - 1) / NTHR; ii++) {
                int idx = tid + ii * NTHR;
                if (idx < KK * 16) {
                    int k = idx >> 4, c = idx & 15;
                    const float* src = X + ((size_t)t * KK + k) * BB + b0 + c * 4;
                    CP16(smem_u32(buf + k * 64 + c * 4), src);
                }
            }
        }
        CP_COMMIT();
    };

    int myfirst = blockIdx.x;
    if (myfirst < ntiles) stage(myfirst, xsA);

    int bufsel = 0;
    for (int tile = myfirst; tile < ntiles; tile += gridDim.x) {
        float* cur = bufsel ? xsB : xsA;
        float* nxt = bufsel ? xsA : xsB;

        __syncthreads();
        bool hasnext = (tile + gridDim.x) < ntiles;
        if (hasnext) { stage(tile + gridDim.x, nxt); CP_WAIT1(); }
        else         { CP_WAIT0(); }
        __syncthreads();

        const int m0 = tile * 64;
        const int t  = m0 >> 12;
        const int b0 = m0 & 4095;

        u64 a0[18], a1[18];
#pragma unroll
        for (int q = 0; q < 9; q++) {
            ulonglong2 bv = bp[q];
            a0[2 * q] = bv.x;     a0[2 * q + 1] = bv.y;
            a1[2 * q] = bv.x;     a1[2 * q + 1] = bv.y;
        }

        if (XTB) {
            const int base0 = lane * 68;
            const int xorp  = (lane >> 3) & 3;
#pragma unroll 2
            for (int k = 0; k < KK; k++) {
                int sw = (((k >> 2) ^ xorp) << 2) + (k & 3);
                u64 x0 = dup2(cur[base0 + sw]);
                u64 x1 = dup2(cur[base0 + 32 * 68 + sw]);
                const ulonglong2* Wk =
                    reinterpret_cast<const ulonglong2*>(Wrow + k * GP);
#pragma unroll
                for (int q = 0; q < 9; q++) {
                    ulonglong2 ww = Wk[q];
                    FMA2A(a0[2 * q],     ww.x, x0);
                    FMA2A(a0[2 * q + 1], ww.y, x0);
                    FMA2A(a1[2 * q],     ww.x, x1);
                    FMA2A(a1[2 * q + 1], ww.y, x1);
                }
            }
        } else {
#pragma unroll 2
            for (int k = 0; k < KK; k++) {
                u64 x0 = dup2(cur[k * 64 + lane]);
                u64 x1 = dup2(cur[k * 64 + lane + 32]);
                const ulonglong2* Wk =
                    reinterpret_cast<const ulonglong2*>(Wrow + k * GP);
#pragma unroll
                for (int q = 0; q < 9; q++) {
                    ulonglong2 ww = Wk[q];
                    FMA2A(a0[2 * q],     ww.x, x0);
                    FMA2A(a0[2 * q + 1], ww.y, x0);
                    FMA2A(a1[2 * q],     ww.x, x1);
                    FMA2A(a1[2 * q + 1], ww.y, x1);
                }
            }
        }

        float* gbase = gx + (size_t)t * GP * BB + b0;
#pragma unroll
        for (int q = 0; q < 18; q++) {
            int c0 = w * 36 + 2 * q;
            float lo, hi;
            unpack2f(a0[q], lo, hi);
            gbase[(size_t)c0 * BB + lane]       = lo;
            gbase[(size_t)(c0 + 1) * BB + lane] = hi;
            unpack2f(a1[q], lo, hi);
            gbase[(size_t)c0 * BB + lane + 32]       = lo;
            gbase[(size_t)(c0 + 1) * BB + lane + 32] = hi;
        }
        bufsel ^= 1;
    }
}

// ---------------------------------------------------------------------------
// Recurrence, 2-CTA cluster: CTA rank owns 36 units (144 gate cols) of all 64
// rows; h exchanged per step via DSMEM; h double-buffered.
// ---------------------------------------------------------------------------
template <bool WRITE_SEQ>
__global__ void __launch_bounds__(RTHR, 1) __cluster_dims__(2, 1, 1)
lstm_rec(const float* __restrict__ gx, const float* __restrict__ Whh,
         float* __restrict__ seq_out, float* __restrict__ fin_out)
{
    extern __shared__ float sm[];
    float* Wb  = sm;                 // [HH][144] local cols
    float* hb0 = Wb + HH * 144;      // [HH][64]
    float* hb1 = hb0 + HH * 64;      // [HH][64]

    const int tid  = threadIdx.x;
    const int lane = tid & 31;
    const int w    = tid >> 5;       // 0..8
    uint32_t rank;
    asm("mov.u32 %0, %%cluster_ctarank;" : "=r"(rank));
    const uint32_t peer = rank ^ 1u;
    const int ubase = 36 * (int)rank;
    const int row0  = (blockIdx.x >> 1) * 64;

    for (int i = tid; i < HH * 144; i += RTHR) Wb[i] = 0.f;
    for (int i = tid; i < 2 * HH * 64; i += RTHR) hb0[i] = 0.f;
    __syncthreads();

    // stage local 144 cols of Whh (gate-interleaved within local units)
    for (int idx = tid; idx < 4 * HH * HH; idx += RTHR) {
        int j = idx / HH, k = idx - j * HH;
        int g = j / HH, n = j - g * HH;
        int ul = n - ubase;
        if (ul >= 0 && ul < 36)
            Wb[k * 144 + 4 * ul + g] = Whh[idx];
    }
    __syncthreads();

    // remote bases for the two h buffers
    const uint32_t rmap0 = mapa_peer(smem_u32(hb0), peer);
    const uint32_t rmap1 = mapa_peer(smem_u32(hb1), peer);

    float cregA[4], cregB[4];
#pragma unroll
    for (int u = 0; u < 4; u++) { cregA[u] = 0.f; cregB[u] = 0.f; }

    // gx: cols 144*rank + 16w + j, rows row0+lane / +32
    const float* gxw = gx + (size_t)(144 * rank + 16 * w) * BB + row0 + lane;

    float cur[32], nxt[32];
#pragma unroll
    for (int j = 0; j < 16; j++) {
        cur[j]      = gxw[(size_t)j * BB];
        cur[16 + j] = gxw[(size_t)j * BB + 32];
    }

    const float* Wrow = Wb + 16 * w;

    CLU_ARRIVE();   // init complete

    for (int t = 0; t < TT; t++) {
        CLU_WAIT();  // h(t-1) writes (local+remote) visible

        const float* hbc = (t & 1) ? hb1 : hb0;
        float*       hbn = (t & 1) ? hb0 : hb1;
        const uint32_t rbase = (t & 1) ? rmap0 : rmap1;

        u64 acc0[8], acc1[8];
#pragma unroll
        for (int q = 0; q < 8; q++) {
            acc0[q] = pack2f(cur[2 * q],      cur[2 * q + 1]);
            acc1[q] = pack2f(cur[16 + 2 * q], cur[17 + 2 * q]);
        }

        if (t + 1 < TT) {
            const float* gn = gxw + (size_t)(t + 1) * GP * BB;
#pragma unroll
            for (int j = 0; j < 16; j++) {
                nxt[j]      = gn[(size_t)j * BB];
                nxt[16 + j] = gn[(size_t)j * BB + 32];
            }
        }

        // GEMM: 16 cols x 64 rows per warp, k = 70
#pragma unroll 2
        for (int k = 0; k < HH; k++) {
            u64 xA = dup2(hbc[k * 64 + lane]);
            u64 xB = dup2(hbc[k * 64 + lane + 32]);
            const ulonglong2* Wk =
                reinterpret_cast<const ulonglong2*>(Wrow + k * 144);
#pragma unroll
            for (int q = 0; q < 4; q++) {
                ulonglong2 ww = Wk[q];
                FMA2A(acc0[2 * q],     ww.x, xA);
                FMA2A(acc0[2 * q + 1], ww.y, xA);
                FMA2A(acc1[2 * q],     ww.x, xB);
                FMA2A(acc1[2 * q + 1], ww.y, xB);
            }
        }

        // cell update: warp w owns local units 4w..4w+3
#pragma unroll
        for (int u = 0; u < 4; u++) {
            int n = ubase + 4 * w + u;
            float giA, gfA, ggA, goA, giB, gfB, ggB, goB;
            unpack2f(acc0[2 * u],     giA, gfA);
            unpack2f(acc0[2 * u + 1], ggA, goA);
            unpack2f(acc1[2 * u],     giB, gfB);
            unpack2f(acc1[2 * u + 1], ggB, goB);

            float cA = __fmaf_rn(sigm(gfA), cregA[u], sigm(giA) * tanh_(ggA));
            float cB = __fmaf_rn(sigm(gfB), cregB[u], sigm(giB) * tanh_(ggB));
            cregA[u] = cA;
            cregB[u] = cB;
            float hA = sigm(goA) * tanh_(cA);
            float hB = sigm(goB) * tanh_(cB);

            if (n < HH) {
                // local
                hbn[n * 64 + lane]      = hA;
                hbn[n * 64 + lane + 32] = hB;
                // remote (peer CTA's copy)
                uint32_t off = (uint32_t)(n * 64 + lane) * 4u;
                STS_CLUSTER(rbase + off, hA);
                STS_CLUSTER(rbase + off + 128u, hB);

                if (WRITE_SEQ) {
                    float* so = seq_out + ((size_t)t * HH + n) * BB + row0 + lane;
                    so[0]  = hA;
                    so[32] = hB;
                }
                if (!WRITE_SEQ && t == TT - 1) {
                    float* fo = fin_out + (size_t)n * BB + row0 + lane;
                    fo[0]  = hA;
                    fo[32] = hB;
                }
            }
        }

        CLU_ARRIVE();   // release h(t) writes (ALL iterations, incl. last)

#pragma unroll
        for (int j = 0; j < 32; j++) cur[j] = nxt[j];
    }

    // exit safety: peer's last remote stores must land before SMEM dealloc
    CLU_WAIT();
}

// head: out = sigmoid(relu(h1 @ W1.T + b1) @ W2.T + b2)
__global__ void __launch_bounds__(256)
head_kernel(const float* __restrict__ h1,
            const float* __restrict__ W1, const float* __restrict__ b1,
            const float* __restrict__ W2, const float* __restrict__ b2,
            float* __restrict__ out)
{
    __shared__ float sW1[50 * HH];
    __shared__ float sb1[50];
    __shared__ float sW2[50];
    __shared__ float sb2;
    for (int i = threadIdx.x; i < 50 * HH; i += 256) sW1[i] = W1[i];
    if (threadIdx.x < 50) {
        sb1[threadIdx.x] = b1[threadIdx.x];
        sW2[threadIdx.x] = W2[threadIdx.x];
    }
    if (threadIdx.x == 0) sb2 = b2[0];
    __syncthreads();

    int row = blockIdx.x * 256 + threadIdx.x;
    float h[HH];
#pragma unroll
    for (int n = 0; n < HH; n++) h[n] = h1[n * BB + row];

    float o = sb2;
    for (int s = 0; s < 50; s++) {
        float a = sb1[s];
#pragma unroll
        for (int n = 0; n < HH; n++) a += h[n] * sW1[s * HH + n];
        a = fmaxf(a, 0.f);
        o += a * sW2[s];
    }
    out[row] = sigm(o);
}

extern "C" void kernel_launch(void* const* d_in, const int* in_sizes, int n_in,
                              void* d_out, int out_size)
{
    int o = (n_in >= 14 && in_sizes[1] == 1) ? 2 : 1;
    const float* data_in = (const float*)d_in[0];
    const float* W_ih0 = (const float*)d_in[o + 0];
    const float* W_hh0 = (const float*)d_in[o + 1];
    const float* b_ih0 = (const float*)d_in[o + 2];
    const float* b_hh0 = (const float*)d_in[o + 3];
    const float* W_ih1 = (const float*)d_in[o + 4];
    const float* W_hh1 = (const float*)d_in[o + 5];
    const float* b_ih1 = (const float*)d_in[o + 6];
    const float* b_hh1 = (const float*)d_in[o + 7];
    const float* W1    = (const float*)d_in[o + 8];
    const float* b1    = (const float*)d_in[o + 9];
    const float* W2    = (const float*)d_in[o + 10];
    const float* b2    = (const float*)d_in[o + 11];

    float *gxp = nullptr, *h0p = nullptr, *h1p = nullptr;
    cudaGetSymbolAddress((void**)&gxp, g_gx);
    cudaGetSymbolAddress((void**)&h0p, g_h0);
    cudaGetSymbolAddress((void**)&h1p, g_h1);

    const int smx0 = ((DD + 1) * GP) * 4 + 2 * (64 * 68) * 4;   // ~109 KB
    const int smx1 = ((HH + 1) * GP) * 4 + 2 * (HH * 64) * 4;   // ~117 KB
    const int smr  = (HH * 144 + 2 * HH * 64) * 4;              // ~76 KB

    cudaFuncSetAttribute((const void*)gemm_x<DD, true>,
                         cudaFuncAttributeMaxDynamicSharedMemorySize, smx0);
    cudaFuncSetAttribute((const void*)gemm_x<HH, false>,
                         cudaFuncAttributeMaxDynamicSharedMemorySize, smx1);
    cudaFuncSetAttribute((const void*)lstm_rec<true>,
                         cudaFuncAttributeMaxDynamicSharedMemorySize, smr);
    cudaFuncSetAttribute((const void*)lstm_rec<false>,
                         cudaFuncAttributeMaxDynamicSharedMemorySize, smr);

    gemm_x<DD, true><<<NPERS, NTHR, smx0>>>(data_in, W_ih0, b_ih0, b_hh0, gxp);
    lstm_rec<true><<<RBLK, RTHR, smr>>>(gxp, W_hh0, h0p, nullptr);
    gemm_x<HH, false><<<NPERS, NTHR, smx1>>>(h0p, W_ih1, b_ih1, b_hh1, gxp);
    lstm_rec<false><<<RBLK, RTHR, smr>>>(gxp, W_hh1, nullptr, h1p);
    head_kernel<<<BB / 256, 256>>>(h1p, W1, b1, W2, b2, (float*)d_out);
}

// round 11
// speedup vs baseline: 1.2226x; 1.2226x over previous
#include <cuda_runtime.h>
#include <cstdint>
#include <cstddef>

// ---------------------------------------------------------------------------
// 2-layer LSTM (T=512, B=4096, D=64, H=70) + MLP head.
// R10: recurrence GEMM transposed — lanes own distinct gate-columns (weights
//      load conflict-free at full crossbar efficiency), rows packed in f32x2.
//      Gates spill through SMEM; cell update adds gx straight from global
//      (coalesced, old layout). gemm_x unchanged from R7.
// ---------------------------------------------------------------------------

#define TT   512
#define BB   4096
#define DD   64
#define HH   70
#define GP   288          // padded gate cols (4*72), col = 4n + gate
#define NTHR 256
#define NPERS 148         // persistent gemm CTAs
#define RBLK 128          // recurrence CTAs, 32 rows each

typedef unsigned long long u64;

// scratch: gate-x buffer [T][288][B] (reused for both layers),
//          h0 sequence [T][70][B], final h1 [70][B]
__device__ float g_gx[(size_t)TT * GP * BB];
__device__ float g_h0[(size_t)TT * HH * BB];
__device__ float g_h1[HH * BB];

#define FMA2A(d, a, b) \
    asm("fma.rn.f32x2 %0, %1, %2, %0;" : "+l"(d) : "l"(a), "l"(b))

#define CP16(dst_u32, src) \
    asm volatile("cp.async.ca.shared.global [%0], [%1], 16;" \
                 :: "r"(dst_u32), "l"(src))
#define CP_COMMIT() asm volatile("cp.async.commit_group;")
#define CP_WAIT0()  asm volatile("cp.async.wait_group 0;")
#define CP_WAIT1()  asm volatile("cp.async.wait_group 1;")

__device__ __forceinline__ u64 dup2(float v) {
    u64 r;
    unsigned int u = __float_as_uint(v);
    asm("mov.b64 %0, {%1,%2};" : "=l"(r) : "r"(u), "r"(u));
    return r;
}
__device__ __forceinline__ void unpack2f(u64 v, float& lo, float& hi) {
    unsigned int a, b;
    asm("mov.b64 {%0,%1}, %2;" : "=r"(a), "=r"(b) : "l"(v));
    lo = __uint_as_float(a);
    hi = __uint_as_float(b);
}

__device__ __forceinline__ float sigm(float x) {
    return __fdividef(1.f, 1.f + __expf(-x));
}
__device__ __forceinline__ float tanh_(float x) {
    return __fdividef(2.f, 1.f + __expf(-2.f * x)) - 1.f;
}

// gate-major row j -> interleaved column
__device__ __forceinline__ int gcol(int j) {
    int g = j / HH, n = j - g * HH;
    return 4 * n + g;
}

__device__ __forceinline__ uint32_t smem_u32(const void* p) {
    return (uint32_t)__cvta_generic_to_shared(p);
}

// ---------------------------------------------------------------------------
// gx = X @ W^T + (b1 + b2), output layout [T][GP][B].  (R7, unchanged)
// ---------------------------------------------------------------------------
template <int KK, bool XTB>
__global__ void __launch_bounds__(NTHR, 1)
gemm_x(const float* __restrict__ X, const float* __restrict__ W,
       const float* __restrict__ b1, const float* __restrict__ b2,
       float* __restrict__ gx)
{
    constexpr int XS_ELEMS = XTB ? (64 * 68) : (KK * 64);

    extern __shared__ float sm[];
    float* Wt   = sm;
    float* bias = Wt + KK * GP;
    float* xsA  = bias + GP;
    float* xsB  = xsA + XS_ELEMS;

    const int tid  = threadIdx.x;
    const int lane = tid & 31;
    const int w    = tid >> 5;

    for (int i = tid; i < (KK + 1) * GP; i += NTHR) sm[i] = 0.f;
    __syncthreads();
    for (int idx = tid; idx < 4 * HH * KK; idx += NTHR) {
        int j = idx / KK, k = idx - j * KK;
        Wt[k * GP + gcol(j)] = W[idx];
    }
    for (int j = tid; j < 4 * HH; j += NTHR)
        bias[gcol(j)] = b1[j] + b2[j];
    __syncthreads();

    const ulonglong2* bp =
        reinterpret_cast<const ulonglong2*>(bias + w * 36);
    const float* Wrow = Wt + w * 36;

    const int ntiles = (TT * BB) / 64;

    auto stage = [&](int tile, float* buf) {
        const int m0 = tile * 64;
        const int t  = m0 >> 12;
        const int b0 = m0 & 4095;
        if (XTB) {
#pragma unroll
            for (int ii = 0; ii < (64 * 16) / NTHR; ii++) {
                int idx = tid + ii * NTHR;
                int r = idx >> 4, c = idx & 15;
                int cs = c ^ ((r >> 3) & 3);
                const float* src = X + ((size_t)t * BB + b0 + r) * KK + c * 4;
                CP16(smem_u32(buf + r * 68 + cs * 4), src);
            }
        } else {
#pragma unroll
            for (int ii = 0; ii < (KK * 16 + NTHR - 1) / NTHR; ii++) {
                int idx = tid + ii * NTHR;
                if (idx < KK * 16) {
                    int k = idx >> 4, c = idx & 15;
                    const float* src = X + ((size_t)t * KK + k) * BB + b0 + c * 4;
                    CP16(smem_u32(buf + k * 64 + c * 4), src);
                }
            }
        }
        CP_COMMIT();
    };

    int myfirst = blockIdx.x;
    if (myfirst < ntiles) stage(myfirst, xsA);

    int bufsel = 0;
    for (int tile = myfirst; tile < ntiles; tile += gridDim.x) {
        float* cur = bufsel ? xsB : xsA;
        float* nxt = bufsel ? xsA : xsB;

        __syncthreads();
        bool hasnext = (tile + gridDim.x) < ntiles;
        if (hasnext) { stage(tile + gridDim.x, nxt); CP_WAIT1(); }
        else         { CP_WAIT0(); }
        __syncthreads();

        const int m0 = tile * 64;
        const int t  = m0 >> 12;
        const int b0 = m0 & 4095;

        u64 a0[18], a1[18];
#pragma unroll
        for (int q = 0; q < 9; q++) {
            ulonglong2 bv = bp[q];
            a0[2 * q] = bv.x;     a0[2 * q + 1] = bv.y;
            a1[2 * q] = bv.x;     a1[2 * q + 1] = bv.y;
        }

        if (XTB) {
            const int base0 = lane * 68;
            const int xorp  = (lane >> 3) & 3;
#pragma unroll 2
            for (int k = 0; k < KK; k++) {
                int sw = (((k >> 2) ^ xorp) << 2) + (k & 3);
                u64 x0 = dup2(cur[base0 + sw]);
                u64 x1 = dup2(cur[base0 + 32 * 68 + sw]);
                const ulonglong2* Wk =
                    reinterpret_cast<const ulonglong2*>(Wrow + k * GP);
#pragma unroll
                for (int q = 0; q < 9; q++) {
                    ulonglong2 ww = Wk[q];
                    FMA2A(a0[2 * q],     ww.x, x0);
                    FMA2A(a0[2 * q + 1], ww.y, x0);
                    FMA2A(a1[2 * q],     ww.x, x1);
                    FMA2A(a1[2 * q + 1], ww.y, x1);
                }
            }
        } else {
#pragma unroll 2
            for (int k = 0; k < KK; k++) {
                u64 x0 = dup2(cur[k * 64 + lane]);
                u64 x1 = dup2(cur[k * 64 + lane + 32]);
                const ulonglong2* Wk =
                    reinterpret_cast<const ulonglong2*>(Wrow + k * GP);
#pragma unroll
                for (int q = 0; q < 9; q++) {
                    ulonglong2 ww = Wk[q];
                    FMA2A(a0[2 * q],     ww.x, x0);
                    FMA2A(a0[2 * q + 1], ww.y, x0);
                    FMA2A(a1[2 * q],     ww.x, x1);
                    FMA2A(a1[2 * q + 1], ww.y, x1);
                }
            }
        }

        float* gbase = gx + (size_t)t * GP * BB + b0;
#pragma unroll
        for (int q = 0; q < 18; q++) {
            int c0 = w * 36 + 2 * q;
            float lo, hi;
            unpack2f(a0[q], lo, hi);
            gbase[(size_t)c0 * BB + lane]       = lo;
            gbase[(size_t)(c0 + 1) * BB + lane] = hi;
            unpack2f(a1[q], lo, hi);
            gbase[(size_t)c0 * BB + lane + 32]       = lo;
            gbase[(size_t)(c0 + 1) * BB + lane + 32] = hi;
        }
        bufsel ^= 1;
    }
}

// ---------------------------------------------------------------------------
// Recurrence (transposed GEMM):
//   GEMM phase : lane owns cols {lane+32j}, warp w owns rows 4w..4w+3 (f32x2
//                row pairs). Weights LDS.32 conflict-free; h LDS.128 bcast.
//   Spill gb, sync, cell update (thread = (unit-group, row)) adds gx from
//   global (coalesced), writes hb + outputs, sync.
// ---------------------------------------------------------------------------
template <bool WRITE_SEQ>
__global__ void __launch_bounds__(NTHR, 1)
lstm_rec(const float* __restrict__ gx, const float* __restrict__ Whh,
         float* __restrict__ seq_out, float* __restrict__ fin_out)
{
    extern __shared__ float sm[];
    float* Ws = sm;                  // [HH][GP]   weights, col = gcol(j)
    float* hb = Ws + HH * GP;        // [HH][32]   h state (rows 0..31)
    float* gb = hb + HH * 32;        // [GP][33]   gate spill

    const int tid  = threadIdx.x;
    const int lane = tid & 31;
    const int w    = tid >> 5;          // 0..7
    const int row0 = blockIdx.x * 32;

    for (int i = tid; i < HH * GP; i += NTHR) Ws[i] = 0.f;
    for (int i = tid; i < HH * 32; i += NTHR) hb[i] = 0.f;
    __syncthreads();

    for (int idx = tid; idx < 4 * HH * HH; idx += NTHR) {
        int j = idx / HH, k = idx - j * HH;
        Ws[k * GP + gcol(j)] = Whh[idx];
    }
    __syncthreads();

    // ---- update-pass identity: this thread handles row r, units 9w..9w+8
    const int r = lane;
    float creg[9];
#pragma unroll
    for (int u = 0; u < 9; u++) creg[u] = 0.f;

    // gx base for this thread's row
    const float* gxr = gx + row0 + r;

    float cur[36], nxt[36];
#pragma unroll
    for (int uu = 0; uu < 9; uu++) {
        int n = 9 * w + uu;
#pragma unroll
        for (int g = 0; g < 4; g++)
            cur[4 * uu + g] =
                (n < HH) ? gxr[(size_t)(4 * n + g) * BB] : 0.f;
    }

    const float* Wl = Ws + lane;   // lane's column base

    for (int t = 0; t < TT; t++) {
        // prefetch next step's gx (independent of recurrence)
        if (t + 1 < TT) {
            const float* gn = gxr + (size_t)(t + 1) * GP * BB;
#pragma unroll
            for (int uu = 0; uu < 9; uu++) {
                int n = 9 * w + uu;
#pragma unroll
                for (int g = 0; g < 4; g++)
                    nxt[4 * uu + g] =
                        (n < HH) ? gn[(size_t)(4 * n + g) * BB] : 0.f;
            }
        }

        // ---- GEMM: acc[2j+p] = rows (4w+2p, 4w+2p+1) of col lane+32j
        u64 acc[18];
#pragma unroll
        for (int q = 0; q < 18; q++) acc[q] = 0ull;

        {
            const float* hrow = hb + 4 * w;
#pragma unroll 2
            for (int k = 0; k < HH; k++) {
                ulonglong2 h2 =
                    *reinterpret_cast<const ulonglong2*>(hrow + k * 32);
                const float* Wk = Wl + k * GP;
#pragma unroll
                for (int j = 0; j < 9; j++) {
                    u64 w2 = dup2(Wk[32 * j]);
                    FMA2A(acc[2 * j],     w2, h2.x);
                    FMA2A(acc[2 * j + 1], w2, h2.y);
                }
            }
        }

        // ---- spill gates: gb[c][4w+u], c = lane + 32j
#pragma unroll
        for (int j = 0; j < 9; j++) {
            int c = lane + 32 * j;
            float v0, v1, v2, v3;
            unpack2f(acc[2 * j],     v0, v1);
            unpack2f(acc[2 * j + 1], v2, v3);
            gb[c * 33 + 4 * w + 0] = v0;
            gb[c * 33 + 4 * w + 1] = v1;
            gb[c * 33 + 4 * w + 2] = v2;
            gb[c * 33 + 4 * w + 3] = v3;
        }
        __syncthreads();   // all GEMM hb reads + spills done

        // ---- cell update: thread (w, r) handles units 9w..9w+8, row r
#pragma unroll
        for (int uu = 0; uu < 9; uu++) {
            int n = 9 * w + uu;
            if (n < HH) {
                float gi = gb[(4 * n + 0) * 33 + r] + cur[4 * uu + 0];
                float gf = gb[(4 * n + 1) * 33 + r] + cur[4 * uu + 1];
                float gg = gb[(4 * n + 2) * 33 + r] + cur[4 * uu + 2];
                float go = gb[(4 * n + 3) * 33 + r] + cur[4 * uu + 3];
                float iv = sigm(gi);
                float fv = sigm(gf);
                float gv = tanh_(gg);
                float ov = sigm(go);
                float c = __fmaf_rn(fv, creg[uu], iv * gv);
                creg[uu] = c;
                float h = ov * tanh_(c);
                hb[n * 32 + r] = h;
                if (WRITE_SEQ)
                    seq_out[((size_t)t * HH + n) * BB + row0 + r] = h;
                if (!WRITE_SEQ && t == TT - 1)
                    fin_out[(size_t)n * BB + row0 + r] = h;
            }
        }
        __syncthreads();   // hb(t) complete before next GEMM

#pragma unroll
        for (int q = 0; q < 36; q++) cur[q] = nxt[q];
    }
}

// head: out = sigmoid(relu(h1 @ W1.T + b1) @ W2.T + b2)
__global__ void __launch_bounds__(256)
head_kernel(const float* __restrict__ h1,
            const float* __restrict__ W1, const float* __restrict__ b1,
            const float* __restrict__ W2, const float* __restrict__ b2,
            float* __restrict__ out)
{
    __shared__ float sW1[50 * HH];
    __shared__ float sb1[50];
    __shared__ float sW2[50];
    __shared__ float sb2;
    for (int i = threadIdx.x; i < 50 * HH; i += 256) sW1[i] = W1[i];
    if (threadIdx.x < 50) {
        sb1[threadIdx.x] = b1[threadIdx.x];
        sW2[threadIdx.x] = W2[threadIdx.x];
    }
    if (threadIdx.x == 0) sb2 = b2[0];
    __syncthreads();

    int row = blockIdx.x * 256 + threadIdx.x;
    float h[HH];
#pragma unroll
    for (int n = 0; n < HH; n++) h[n] = h1[n * BB + row];

    float o = sb2;
    for (int s = 0; s < 50; s++) {
        float a = sb1[s];
#pragma unroll
        for (int n = 0; n < HH; n++) a += h[n] * sW1[s * HH + n];
        a = fmaxf(a, 0.f);
        o += a * sW2[s];
    }
    out[row] = sigm(o);
}

extern "C" void kernel_launch(void* const* d_in, const int* in_sizes, int n_in,
                              void* d_out, int out_size)
{
    int o = (n_in >= 14 && in_sizes[1] == 1) ? 2 : 1;
    const float* data_in = (const float*)d_in[0];
    const float* W_ih0 = (const float*)d_in[o + 0];
    const float* W_hh0 = (const float*)d_in[o + 1];
    const float* b_ih0 = (const float*)d_in[o + 2];
    const float* b_hh0 = (const float*)d_in[o + 3];
    const float* W_ih1 = (const float*)d_in[o + 4];
    const float* W_hh1 = (const float*)d_in[o + 5];
    const float* b_ih1 = (const float*)d_in[o + 6];
    const float* b_hh1 = (const float*)d_in[o + 7];
    const float* W1    = (const float*)d_in[o + 8];
    const float* b1    = (const float*)d_in[o + 9];
    const float* W2    = (const float*)d_in[o + 10];
    const float* b2    = (const float*)d_in[o + 11];

    float *gxp = nullptr, *h0p = nullptr, *h1p = nullptr;
    cudaGetSymbolAddress((void**)&gxp, g_gx);
    cudaGetSymbolAddress((void**)&h0p, g_h0);
    cudaGetSymbolAddress((void**)&h1p, g_h1);

    const int smx0 = ((DD + 1) * GP) * 4 + 2 * (64 * 68) * 4;   // ~109 KB
    const int smx1 = ((HH + 1) * GP) * 4 + 2 * (HH * 64) * 4;   // ~117 KB
    const int smr  = (HH * GP + HH * 32 + GP * 33) * 4;         // ~125 KB

    cudaFuncSetAttribute((const void*)gemm_x<DD, true>,
                         cudaFuncAttributeMaxDynamicSharedMemorySize, smx0);
    cudaFuncSetAttribute((const void*)gemm_x<HH, false>,
                         cudaFuncAttributeMaxDynamicSharedMemorySize, smx1);
    cudaFuncSetAttribute((const void*)lstm_rec<true>,
                         cudaFuncAttributeMaxDynamicSharedMemorySize, smr);
    cudaFuncSetAttribute((const void*)lstm_rec<false>,
                         cudaFuncAttributeMaxDynamicSharedMemorySize, smr);

    gemm_x<DD, true><<<NPERS, NTHR, smx0>>>(data_in, W_ih0, b_ih0, b_hh0, gxp);
    lstm_rec<true><<<RBLK, NTHR, smr>>>(gxp, W_hh0, h0p, nullptr);
    gemm_x<HH, false><<<NPERS, NTHR, smx1>>>(h0p, W_ih1, b_ih1, b_hh1, gxp);
    lstm_rec<false><<<RBLK, NTHR, smr>>>(gxp, W_hh1, nullptr, h1p);
    head_kernel<<<BB / 256, 256>>>(h1p, W1, b1, W2, b2, (float*)d_out);
}

// round 12
// speedup vs baseline: 1.3262x; 1.0847x over previous
#include <cuda_runtime.h>
#include <cstdint>
#include <cstddef>

// ---------------------------------------------------------------------------
// 2-layer LSTM (T=512, B=4096, D=64, H=70) + MLP head.
// R11: recurrence split-k across 16 warps (512 threads): warp w = row-quad
//      4(w&7), k-half (w>>3); two gate spill buffers summed in update pass.
//      Transposed GEMM layout from R10 (conflict-free weight LDS.32).
//      gemm_x unchanged from R7.
// ---------------------------------------------------------------------------

#define TT   512
#define BB   4096
#define DD   64
#define HH   70
#define GP   288          // padded gate cols (4*72), col = 4n + gate
#define NTHR 256
#define NPERS 148         // persistent gemm CTAs
#define RTHR 512          // recurrence threads (16 warps)
#define RBLK 128          // recurrence CTAs, 32 rows each

typedef unsigned long long u64;

// scratch: gate-x buffer [T][288][B] (reused for both layers),
//          h0 sequence [T][70][B], final h1 [70][B]
__device__ float g_gx[(size_t)TT * GP * BB];
__device__ float g_h0[(size_t)TT * HH * BB];
__device__ float g_h1[HH * BB];

#define FMA2A(d, a, b) \
    asm("fma.rn.f32x2 %0, %1, %2, %0;" : "+l"(d) : "l"(a), "l"(b))

#define CP16(dst_u32, src) \
    asm volatile("cp.async.ca.shared.global [%0], [%1], 16;" \
                 :: "r"(dst_u32), "l"(src))
#define CP_COMMIT() asm volatile("cp.async.commit_group;")
#define CP_WAIT0()  asm volatile("cp.async.wait_group 0;")
#define CP_WAIT1()  asm volatile("cp.async.wait_group 1;")

__device__ __forceinline__ u64 dup2(float v) {
    u64 r;
    unsigned int u = __float_as_uint(v);
    asm("mov.b64 %0, {%1,%2};" : "=l"(r) : "r"(u), "r"(u));
    return r;
}
__device__ __forceinline__ void unpack2f(u64 v, float& lo, float& hi) {
    unsigned int a, b;
    asm("mov.b64 {%0,%1}, %2;" : "=r"(a), "=r"(b) : "l"(v));
    lo = __uint_as_float(a);
    hi = __uint_as_float(b);
}

__device__ __forceinline__ float sigm(float x) {
    return __fdividef(1.f, 1.f + __expf(-x));
}
__device__ __forceinline__ float tanh_(float x) {
    return __fdividef(2.f, 1.f + __expf(-2.f * x)) - 1.f;
}

// gate-major row j -> interleaved column
__device__ __forceinline__ int gcol(int j) {
    int g = j / HH, n = j - g * HH;
    return 4 * n + g;
}

__device__ __forceinline__ uint32_t smem_u32(const void* p) {
    return (uint32_t)__cvta_generic_to_shared(p);
}

// ---------------------------------------------------------------------------
// gx = X @ W^T + (b1 + b2), output layout [T][GP][B].  (R7, unchanged)
// ---------------------------------------------------------------------------
template <int KK, bool XTB>
__global__ void __launch_bounds__(NTHR, 1)
gemm_x(const float* __restrict__ X, const float* __restrict__ W,
       const float* __restrict__ b1, const float* __restrict__ b2,
       float* __restrict__ gx)
{
    constexpr int XS_ELEMS = XTB ? (64 * 68) : (KK * 64);

    extern __shared__ float sm[];
    float* Wt   = sm;
    float* bias = Wt + KK * GP;
    float* xsA  = bias + GP;
    float* xsB  = xsA + XS_ELEMS;

    const int tid  = threadIdx.x;
    const int lane = tid & 31;
    const int w    = tid >> 5;

    for (int i = tid; i < (KK + 1) * GP; i += NTHR) sm[i] = 0.f;
    __syncthreads();
    for (int idx = tid; idx < 4 * HH * KK; idx += NTHR) {
        int j = idx / KK, k = idx - j * KK;
        Wt[k * GP + gcol(j)] = W[idx];
    }
    for (int j = tid; j < 4 * HH; j += NTHR)
        bias[gcol(j)] = b1[j] + b2[j];
    __syncthreads();

    const ulonglong2* bp =
        reinterpret_cast<const ulonglong2*>(bias + w * 36);
    const float* Wrow = Wt + w * 36;

    const int ntiles = (TT * BB) / 64;

    auto stage = [&](int tile, float* buf) {
        const int m0 = tile * 64;
        const int t  = m0 >> 12;
        const int b0 = m0 & 4095;
        if (XTB) {
#pragma unroll
            for (int ii = 0; ii < (64 * 16) / NTHR; ii++) {
                int idx = tid + ii * NTHR;
                int r = idx >> 4, c = idx & 15;
                int cs = c ^ ((r >> 3) & 3);
                const float* src = X + ((size_t)t * BB + b0 + r) * KK + c * 4;
                CP16(smem_u32(buf + r * 68 + cs * 4), src);
            }
        } else {
#pragma unroll
            for (int ii = 0; ii < (KK * 16 + NTHR - 1) / NTHR; ii++) {
                int idx = tid + ii * NTHR;
                if (idx < KK * 16) {
                    int k = idx >> 4, c = idx & 15;
                    const float* src = X + ((size_t)t * KK + k) * BB + b0 + c * 4;
                    CP16(smem_u32(buf + k * 64 + c * 4), src);
                }
            }
        }
        CP_COMMIT();
    };

    int myfirst = blockIdx.x;
    if (myfirst < ntiles) stage(myfirst, xsA);

    int bufsel = 0;
    for (int tile = myfirst; tile < ntiles; tile += gridDim.x) {
        float* cur = bufsel ? xsB : xsA;
        float* nxt = bufsel ? xsA : xsB;

        __syncthreads();
        bool hasnext = (tile + gridDim.x) < ntiles;
        if (hasnext) { stage(tile + gridDim.x, nxt); CP_WAIT1(); }
        else         { CP_WAIT0(); }
        __syncthreads();

        const int m0 = tile * 64;
        const int t  = m0 >> 12;
        const int b0 = m0 & 4095;

        u64 a0[18], a1[18];
#pragma unroll
        for (int q = 0; q < 9; q++) {
            ulonglong2 bv = bp[q];
            a0[2 * q] = bv.x;     a0[2 * q + 1] = bv.y;
            a1[2 * q] = bv.x;     a1[2 * q + 1] = bv.y;
        }

        if (XTB) {
            const int base0 = lane * 68;
            const int xorp  = (lane >> 3) & 3;
#pragma unroll 2
            for (int k = 0; k < KK; k++) {
                int sw = (((k >> 2) ^ xorp) << 2) + (k & 3);
                u64 x0 = dup2(cur[base0 + sw]);
                u64 x1 = dup2(cur[base0 + 32 * 68 + sw]);
                const ulonglong2* Wk =
                    reinterpret_cast<const ulonglong2*>(Wrow + k * GP);
#pragma unroll
                for (int q = 0; q < 9; q++) {
                    ulonglong2 ww = Wk[q];
                    FMA2A(a0[2 * q],     ww.x, x0);
                    FMA2A(a0[2 * q + 1], ww.y, x0);
                    FMA2A(a1[2 * q],     ww.x, x1);
                    FMA2A(a1[2 * q + 1], ww.y, x1);
                }
            }
        } else {
#pragma unroll 2
            for (int k = 0; k < KK; k++) {
                u64 x0 = dup2(cur[k * 64 + lane]);
                u64 x1 = dup2(cur[k * 64 + lane + 32]);
                const ulonglong2* Wk =
                    reinterpret_cast<const ulonglong2*>(Wrow + k * GP);
#pragma unroll
                for (int q = 0; q < 9; q++) {
                    ulonglong2 ww = Wk[q];
                    FMA2A(a0[2 * q],     ww.x, x0);
                    FMA2A(a0[2 * q + 1], ww.y, x0);
                    FMA2A(a1[2 * q],     ww.x, x1);
                    FMA2A(a1[2 * q + 1], ww.y, x1);
                }
            }
        }

        float* gbase = gx + (size_t)t * GP * BB + b0;
#pragma unroll
        for (int q = 0; q < 18; q++) {
            int c0 = w * 36 + 2 * q;
            float lo, hi;
            unpack2f(a0[q], lo, hi);
            gbase[(size_t)c0 * BB + lane]       = lo;
            gbase[(size_t)(c0 + 1) * BB + lane] = hi;
            unpack2f(a1[q], lo, hi);
            gbase[(size_t)c0 * BB + lane + 32]       = lo;
            gbase[(size_t)(c0 + 1) * BB + lane + 32] = hi;
        }
        bufsel ^= 1;
    }
}

// ---------------------------------------------------------------------------
// Recurrence (split-k transposed GEMM, 16 warps):
//   warp w: row-quad 4(w&7), k-half (w>>3), lane owns cols {lane+32j}.
//   Spill to gbA/gbB by k-half; update pass sums gbA+gbB+gx (prefetched).
// ---------------------------------------------------------------------------
#define UPD_ITERS ((HH * 32 + RTHR - 1) / RTHR)   // 5

template <bool WRITE_SEQ>
__global__ void __launch_bounds__(RTHR, 1)
lstm_rec(const float* __restrict__ gx, const float* __restrict__ Whh,
         float* __restrict__ seq_out, float* __restrict__ fin_out)
{
    extern __shared__ float sm[];
    float* Ws  = sm;                  // [HH][GP]   weights, col = gcol(j)
    float* hb  = Ws + HH * GP;        // [HH][32]   h state
    float* gbA = hb + HH * 32;        // [GP][33]   gate spill, k-half 0
    float* gbB = gbA + GP * 33;       // [GP][33]   gate spill, k-half 1

    const int tid  = threadIdx.x;
    const int lane = tid & 31;
    const int w    = tid >> 5;          // 0..15
    const int wr   = w & 7;             // row-quad index
    const int kh   = w >> 3;            // k-half
    const int row0 = blockIdx.x * 32;

    for (int i = tid; i < HH * GP; i += RTHR) Ws[i] = 0.f;
    for (int i = tid; i < HH * 32; i += RTHR) hb[i] = 0.f;
    __syncthreads();

    for (int idx = tid; idx < 4 * HH * HH; idx += RTHR) {
        int j = idx / HH, k = idx - j * HH;
        Ws[k * GP + gcol(j)] = Whh[idx];
    }
    __syncthreads();

    float creg[UPD_ITERS];
#pragma unroll
    for (int i = 0; i < UPD_ITERS; i++) creg[i] = 0.f;

    // GEMM bases for this warp's k-half
    const float* Wl0 = Ws + lane + (kh ? 35 * GP : 0);
    const float* hr0 = hb + 4 * wr + (kh ? 35 * 32 : 0);
    float* gb = kh ? gbB : gbA;

    for (int t = 0; t < TT; t++) {
        // ---- prefetch this step's gx for the update pass (coalesced LDG)
        float cur[UPD_ITERS][4];
        {
            const float* gxt = gx + (size_t)t * GP * BB + row0;
#pragma unroll
            for (int i = 0; i < UPD_ITERS; i++) {
                int idx = tid + i * RTHR;
                if (idx < HH * 32) {
                    int n = idx >> 5, r = idx & 31;
#pragma unroll
                    for (int g = 0; g < 4; g++)
                        cur[i][g] = gxt[(size_t)(4 * n + g) * BB + r];
                }
            }
        }

        // ---- GEMM (35 k-iters): acc[2j+p] = row pair of col lane+32j
        u64 acc[18];
#pragma unroll
        for (int q = 0; q < 18; q++) acc[q] = 0ull;

#pragma unroll 5
        for (int k = 0; k < 35; k++) {
            ulonglong2 h2 =
                *reinterpret_cast<const ulonglong2*>(hr0 + k * 32);
            const float* Wk = Wl0 + k * GP;
#pragma unroll
            for (int j = 0; j < 9; j++) {
                u64 w2 = dup2(Wk[32 * j]);
                FMA2A(acc[2 * j],     w2, h2.x);
                FMA2A(acc[2 * j + 1], w2, h2.y);
            }
        }

        // ---- spill gates: gb[c][4wr+u], c = lane + 32j
#pragma unroll
        for (int j = 0; j < 9; j++) {
            int c = lane + 32 * j;
            float v0, v1, v2, v3;
            unpack2f(acc[2 * j],     v0, v1);
            unpack2f(acc[2 * j + 1], v2, v3);
            gb[c * 33 + 4 * wr + 0] = v0;
            gb[c * 33 + 4 * wr + 1] = v1;
            gb[c * 33 + 4 * wr + 2] = v2;
            gb[c * 33 + 4 * wr + 3] = v3;
        }
        __syncthreads();   // GEMM hb reads + both spills complete

        // ---- cell update: flat over (unit, row)
#pragma unroll
        for (int i = 0; i < UPD_ITERS; i++) {
            int idx = tid + i * RTHR;
            if (idx < HH * 32) {
                int n = idx >> 5, r = idx & 31;
                float gi = gbA[(4 * n + 0) * 33 + r] + gbB[(4 * n + 0) * 33 + r] + cur[i][0];
                float gf = gbA[(4 * n + 1) * 33 + r] + gbB[(4 * n + 1) * 33 + r] + cur[i][1];
                float gg = gbA[(4 * n + 2) * 33 + r] + gbB[(4 * n + 2) * 33 + r] + cur[i][2];
                float go = gbA[(4 * n + 3) * 33 + r] + gbB[(4 * n + 3) * 33 + r] + cur[i][3];
                float iv = sigm(gi);
                float fv = sigm(gf);
                float gv = tanh_(gg);
                float ov = sigm(go);
                float c = __fmaf_rn(fv, creg[i], iv * gv);
                creg[i] = c;
                float h = ov * tanh_(c);
                hb[n * 32 + r] = h;
                if (WRITE_SEQ)
                    seq_out[((size_t)t * HH + n) * BB + row0 + r] = h;
                if (!WRITE_SEQ && t == TT - 1)
                    fin_out[(size_t)n * BB + row0 + r] = h;
            }
        }
        __syncthreads();   // hb(t) ready, gb consumed, before next spill
    }
}

// head: out = sigmoid(relu(h1 @ W1.T + b1) @ W2.T + b2)
__global__ void __launch_bounds__(256)
head_kernel(const float* __restrict__ h1,
            const float* __restrict__ W1, const float* __restrict__ b1,
            const float* __restrict__ W2, const float* __restrict__ b2,
            float* __restrict__ out)
{
    __shared__ float sW1[50 * HH];
    __shared__ float sb1[50];
    __shared__ float sW2[50];
    __shared__ float sb2;
    for (int i = threadIdx.x; i < 50 * HH; i += 256) sW1[i] = W1[i];
    if (threadIdx.x < 50) {
        sb1[threadIdx.x] = b1[threadIdx.x];
        sW2[threadIdx.x] = W2[threadIdx.x];
    }
    if (threadIdx.x == 0) sb2 = b2[0];
    __syncthreads();

    int row = blockIdx.x * 256 + threadIdx.x;
    float h[HH];
#pragma unroll
    for (int n = 0; n < HH; n++) h[n] = h1[n * BB + row];

    float o = sb2;
    for (int s = 0; s < 50; s++) {
        float a = sb1[s];
#pragma unroll
        for (int n = 0; n < HH; n++) a += h[n] * sW1[s * HH + n];
        a = fmaxf(a, 0.f);
        o += a * sW2[s];
    }
    out[row] = sigm(o);
}

extern "C" void kernel_launch(void* const* d_in, const int* in_sizes, int n_in,
                              void* d_out, int out_size)
{
    int o = (n_in >= 14 && in_sizes[1] == 1) ? 2 : 1;
    const float* data_in = (const float*)d_in[0];
    const float* W_ih0 = (const float*)d_in[o + 0];
    const float* W_hh0 = (const float*)d_in[o + 1];
    const float* b_ih0 = (const float*)d_in[o + 2];
    const float* b_hh0 = (const float*)d_in[o + 3];
    const float* W_ih1 = (const float*)d_in[o + 4];
    const float* W_hh1 = (const float*)d_in[o + 5];
    const float* b_ih1 = (const float*)d_in[o + 6];
    const float* b_hh1 = (const float*)d_in[o + 7];
    const float* W1    = (const float*)d_in[o + 8];
    const float* b1    = (const float*)d_in[o + 9];
    const float* W2    = (const float*)d_in[o + 10];
    const float* b2    = (const float*)d_in[o + 11];

    float *gxp = nullptr, *h0p = nullptr, *h1p = nullptr;
    cudaGetSymbolAddress((void**)&gxp, g_gx);
    cudaGetSymbolAddress((void**)&h0p, g_h0);
    cudaGetSymbolAddress((void**)&h1p, g_h1);

    const int smx0 = ((DD + 1) * GP) * 4 + 2 * (64 * 68) * 4;   // ~109 KB
    const int smx1 = ((HH + 1) * GP) * 4 + 2 * (HH * 64) * 4;   // ~117 KB
    const int smr  = (HH * GP + HH * 32 + 2 * GP * 33) * 4;     // ~162 KB

    cudaFuncSetAttribute((const void*)gemm_x<DD, true>,
                         cudaFuncAttributeMaxDynamicSharedMemorySize, smx0);
    cudaFuncSetAttribute((const void*)gemm_x<HH, false>,
                         cudaFuncAttributeMaxDynamicSharedMemorySize, smx1);
    cudaFuncSetAttribute((const void*)lstm_rec<true>,
                         cudaFuncAttributeMaxDynamicSharedMemorySize, smr);
    cudaFuncSetAttribute((const void*)lstm_rec<false>,
                         cudaFuncAttributeMaxDynamicSharedMemorySize, smr);

    gemm_x<DD, true><<<NPERS, NTHR, smx0>>>(data_in, W_ih0, b_ih0, b_hh0, gxp);
    lstm_rec<true><<<RBLK, RTHR, smr>>>(gxp, W_hh0, h0p, nullptr);
    gemm_x<HH, false><<<NPERS, NTHR, smx1>>>(h0p, W_ih1, b_ih1, b_hh1, gxp);
    lstm_rec<false><<<RBLK, RTHR, smr>>>(gxp, W_hh1, nullptr, h1p);
    head_kernel<<<BB / 256, 256>>>(h1p, W1, b1, W2, b2, (float*)d_out);
}